// round 15
// baseline (speedup 1.0000x reference)
#include <cuda_runtime.h>
#include <math.h>
#include <stdint.h>

#define Bn 16
#define Nn 1000
#define En 16000
#define NT 16000
#define EBASE 256000
#define ETOT 272000
#define TWOE 32000
#define HALFB 8
#define NLOW 8000         /* dsts 0..7999 have only their self loop (structural) */

#define H1n 8
#define F1 1024
#define EMBn 64
#define HIDn 128
#define BCAP 96

#define NCHUNK 400
#define CK 160

// ------------------------- scratch -------------------------
__device__ __align__(16) float4 g_xf[NT];
__device__ float g_psrc[24];
__device__ float g_pdst[24];
__device__ int   g_cursor[NT];                 // zero at load; re-zeroed in mlp1
__device__ int   g_bucket[NT * BCAP];
__device__ __align__(16) float g_s[NT * 24];
__device__ __align__(16) float g_h2[NT * EMBn];
__device__ float g_a2s[NT];
__device__ float g_a2d[NT];
__device__ __align__(16) float g_x2t[64000 * 16];
__device__ float g_part[NCHUNK * 16 * HIDn];
__device__ float g_y1[16 * HIDn];

// ------------------------- helpers -------------------------
__device__ __forceinline__ void edge_sd(int e, const int* __restrict__ EI, int& src, int& dst) {
    if (e < EBASE) {
        int b   = e / TWOE;
        int rem = e - b * TWOE;
        src = EI[b * TWOE + rem] + b * Nn;
        int b2 = b + HALFB;
        dst = EI[b2 * TWOE + rem] + b2 * Nn;
    } else {
        src = dst = e - EBASE;
    }
}

__device__ __forceinline__ float warp_sum(float v) {
    #pragma unroll
    for (int o = 16; o > 0; o >>= 1) v += __shfl_xor_sync(0xffffffffu, v, o);
    return v;
}
__device__ __forceinline__ float leaky(float v) { return v > 0.f ? v : 0.2f * v; }
__device__ __forceinline__ float elu(float v)   { return v > 0.f ? v : (__expf(v) - 1.0f); }

__device__ __forceinline__ float2 ffma2(float2 a, float2 b, float2 c) {
    unsigned long long A = *reinterpret_cast<unsigned long long*>(&a);
    unsigned long long B = *reinterpret_cast<unsigned long long*>(&b);
    unsigned long long C = *reinterpret_cast<unsigned long long*>(&c);
    unsigned long long D;
    asm("fma.rn.f32x2 %0, %1, %2, %3;" : "=l"(D) : "l"(A), "l"(B), "l"(C));
    return *reinterpret_cast<float2*>(&D);
}

// ================= build: node features + projections + bucket scatter =================
__global__ void build_kernel(const float* __restrict__ actions,
                             const float* __restrict__ nodef,
                             const float* __restrict__ W1,
                             const float* __restrict__ as1,
                             const float* __restrict__ ad1,
                             const int* __restrict__ EI) {
    int blk = blockIdx.x;
    if (blk < 63) {
        int n = blk * 256 + threadIdx.x;
        if (n >= NT) return;
        float ax = actions[n * 2 + 0];
        float ay = actions[n * 2 + 1];
        float nf = nodef[n];
        g_xf[n] = make_float4(ax, ay, nf, 0.f);
    } else if (blk == 63) {
        int t = threadIdx.x;
        if (t < 48) {
            int which = t / 24;
            int r = t % 24;
            int k = r / 8, h = r % 8;
            const float* att = which ? ad1 : as1;
            float s = 0.f;
            for (int c = 0; c < 128; c++)
                s += W1[k * F1 + h * 128 + c] * att[h * 128 + c];
            (which ? g_pdst : g_psrc)[k * 8 + h] = s;
        }
    } else {
        int idx = (blk - 64) * 256 + threadIdx.x;
        #pragma unroll
        for (int q = 0; q < 4; q++) {
            int e = idx * 4 + q;
            if (e < ETOT) {
                int src, dst;
                edge_sd(e, EI, src, dst);
                if (dst >= NLOW) {
                    int pos = atomicAdd(&g_cursor[dst], 1);
                    g_bucket[dst * BCAP + pos] = src;
                }
            }
        }
    }
}

// ================= conv1: thread per (dst, head); low half = identity =================
__global__ __launch_bounds__(256) void conv1_kernel() {
    int gidx = blockIdx.x * 256 + threadIdx.x;
    if (gidx < 8000) {
        int d = gidx;
        float4 x = g_xf[d];
        float4 v0 = make_float4(x.x, x.y, x.z, x.x);
        float4 v1 = make_float4(x.y, x.z, x.x, x.y);
        float4 v2 = make_float4(x.z, x.x, x.y, x.z);
        float4* sp = (float4*)(g_s + d * 24);
        sp[0] = v0; sp[1] = v1; sp[2] = v2;
        sp[3] = v0; sp[4] = v1; sp[5] = v2;
    } else if (gidx < 8000 + 64000) {
        int i2 = gidx - 8000;
        int d = NLOW + (i2 >> 3), h = i2 & 7;
        float4 xd = g_xf[d];
        float p0 = g_psrc[h], p1 = g_psrc[8 + h], p2 = g_psrc[16 + h];
        float q0 = g_pdst[h], q1 = g_pdst[8 + h], q2 = g_pdst[16 + h];
        float adv = fmaf(xd.x, q0, fmaf(xd.y, q1, xd.z * q2));
        int deg = g_cursor[d];
        const int* bkt = g_bucket + d * BCAP;
        float se = 0.f, sx = 0.f, sy = 0.f, sz = 0.f;
        for (int e = 0; e < deg; e++) {
            int s = bkt[e];
            float4 x = g_xf[s];
            float a = fmaf(x.x, p0, fmaf(x.y, p1, x.z * p2)) + adv;
            float ea = __expf(leaky(a));
            se += ea;
            sx = fmaf(ea, x.x, sx);
            sy = fmaf(ea, x.y, sy);
            sz = fmaf(ea, x.z, sz);
        }
        float inv = 1.0f / se;
        float* sp = g_s + d * 24 + h * 3;
        sp[0] = sx * inv; sp[1] = sy * inv; sp[2] = sz * inv;
    }
}

// ================= fgemm: broadcast-GEMM, 64 rows/CTA, 2 CTAs/SM =================
// 250 blocks x 256 threads; block covers 64 rows.
// slot = tid&63 -> row; group = tid>>6 (warp-uniform) -> 16-col group.
// Per k: 1 broadcast w1t float4 + x1 build + 4 broadcast W2 float4 + 8 FFMA2.
#define FS_W1T 0
#define FS_W2C 16384
#define FS_SS  (FS_W2C + 32768)
#define FS_ATT (FS_SS + 6144)
#define FS_TOTAL (FS_ATT + 512)

__global__ __launch_bounds__(256, 2) void fgemm_kernel(
    const float* __restrict__ W1, const float* __restrict__ b1,
    const float* __restrict__ W2, const float* __restrict__ as2,
    const float* __restrict__ ad2)
{
    extern __shared__ __align__(16) char dsm[];
    float4* w1t = (float4*)(dsm + FS_W1T);
    float*  w2c = (float*)(dsm + FS_W2C);     // [128][64] chunk (reused as reduce scratch)
    float*  sS  = (float*)(dsm + FS_SS);      // 64 rows x 24
    float*  att = (float*)(dsm + FS_ATT);

    int tid = threadIdx.x;
    int bid = blockIdx.x;
    int slot = tid & 63;
    int group = tid >> 6;                     // warp-uniform (warps 0,1->g0 ... 6,7->g3)
    int row = bid * 64 + slot;

    for (int k = tid; k < F1; k += 256)
        w1t[k] = make_float4(W1[k], W1[F1 + k], W1[2 * F1 + k], b1[k]);
    for (int i = tid; i < 64 * 24; i += 256)
        sS[i] = g_s[bid * 64 * 24 + i];
    if (tid < 128) att[tid] = (tid < 64) ? as2[tid] : ad2[tid - 64];

    float2 acc[8];
    #pragma unroll
    for (int j = 0; j < 8; j++) acc[j] = make_float2(0.f, 0.f);

    for (int ch = 0; ch < 8; ch++) {
        __syncthreads();
        {   // stage W2 chunk: 128 k-rows x 64 cols = 2048 float4
            const float4* w2g = (const float4*)(W2 + ch * 128 * EMBn);
            float4* w2s = (float4*)w2c;
            #pragma unroll
            for (int i = 0; i < 8; i++)
                w2s[tid + i * 256] = w2g[tid + i * 256];
        }
        __syncthreads();
        float s0 = sS[slot * 24 + ch * 3 + 0];
        float s1 = sS[slot * 24 + ch * 3 + 1];
        float s2 = sS[slot * 24 + ch * 3 + 2];
        const float* wc = w2c + group * 16;
        #pragma unroll 4
        for (int k = 0; k < 128; k++) {
            float4 w = w1t[ch * 128 + k];                       // broadcast
            float x1 = fmaf(s0, w.x, fmaf(s1, w.y, fmaf(s2, w.z, w.w)));
            x1 = elu(x1);
            float2 xx = make_float2(x1, x1);
            const float4* brow = (const float4*)(wc + k * 64);  // broadcast per group
            float4 b0 = brow[0];
            float4 b1v = brow[1];
            float4 b2v = brow[2];
            float4 b3 = brow[3];
            acc[0] = ffma2(xx, make_float2(b0.x, b0.y), acc[0]);
            acc[1] = ffma2(xx, make_float2(b0.z, b0.w), acc[1]);
            acc[2] = ffma2(xx, make_float2(b1v.x, b1v.y), acc[2]);
            acc[3] = ffma2(xx, make_float2(b1v.z, b1v.w), acc[3]);
            acc[4] = ffma2(xx, make_float2(b2v.x, b2v.y), acc[4]);
            acc[5] = ffma2(xx, make_float2(b2v.z, b2v.w), acc[5]);
            acc[6] = ffma2(xx, make_float2(b3.x, b3.y), acc[6]);
            acc[7] = ffma2(xx, make_float2(b3.z, b3.w), acc[7]);
        }
    }

    // store h2 (16 cols per thread)
    {
        float4* dst = (float4*)(g_h2 + row * 64 + group * 16);
        const float4* a4 = (const float4*)acc;
        #pragma unroll
        for (int j = 0; j < 4; j++) dst[j] = a4[j];
    }
    // attn2: per-thread partials over its 16 cols; combine 4 groups via smem
    float ss = 0.f, sd = 0.f;
    {
        const float* av = (const float*)acc;
        #pragma unroll
        for (int j = 0; j < 16; j++) {
            float v = av[j];
            ss = fmaf(v, att[group * 16 + j], ss);
            sd = fmaf(v, att[64 + group * 16 + j], sd);
        }
    }
    __syncthreads();
    float* red = w2c;                          // reuse chunk buffer
    red[tid] = ss; red[256 + tid] = sd;
    __syncthreads();
    if (tid < 64) {
        g_a2s[row] = red[tid] + red[tid + 64] + red[tid + 128] + red[tid + 192];
        g_a2d[row] = red[256 + tid] + red[256 + tid + 64] + red[256 + tid + 128] + red[256 + tid + 192];
    }
}

// ================= conv2: warp per heavy dst; low half elementwise =================
__global__ __launch_bounds__(256) void conv2_kernel(const float* __restrict__ b2) {
    __shared__ float wbuf[8][BCAP];
    __shared__ int   ibuf[8][BCAP];
    int tid = threadIdx.x;
    int gidx = blockIdx.x * 256 + tid;
    int lane = tid & 31;
    int w = tid >> 5;
    int wg = gidx >> 5;                         // 8000 warps
    {
        int d = NLOW + wg;
        int deg = g_cursor[d];
        const int* bkt = g_bucket + d * BCAP;
        float adv = g_a2d[d];
        float se = 0.f;
        for (int e = lane; e < deg; e += 32) {
            int src = bkt[e];
            float ea = __expf(leaky(g_a2s[src] + adv));
            wbuf[w][e] = ea;
            ibuf[w][e] = src;
            se += ea;
        }
        __syncwarp();
        float2 acc = make_float2(0.f, 0.f);
        #pragma unroll 4
        for (int e = 0; e < deg; e++) {
            float ea = wbuf[w][e];
            int src = ibuf[w][e];
            float2 v = ((const float2*)(g_h2 + src * 64))[lane];
            acc.x = fmaf(ea, v.x, acc.x);
            acc.y = fmaf(ea, v.y, acc.y);
        }
        __syncwarp();
        se = warp_sum(se);
        float inv = 1.0f / se;
        float2 bb = ((const float2*)b2)[lane];
        int b = d / Nn, n = d - b * Nn;
        int c = lane * 2;
        g_x2t[(n * 64 + c) * 16 + b]     = elu(acc.x * inv + bb.x);
        g_x2t[(n * 64 + c + 1) * 16 + b] = elu(acc.y * inv + bb.y);
    }
    {   // low half: 8000*32 threads exactly
        int d = gidx >> 5, ln = gidx & 31;
        float2 v = ((const float2*)(g_h2 + d * 64))[ln];
        float2 bb = ((const float2*)b2)[ln];
        int b = d / Nn, n = d - b * Nn;
        int c = ln * 2;
        g_x2t[(n * 64 + c) * 16 + b]     = elu(v.x + bb.x);
        g_x2t[(n * 64 + c + 1) * 16 + b] = elu(v.y + bb.y);
    }
}

// ================= mlp1 split-K stage 1 (+ cursor reset) =================
__global__ __launch_bounds__(128) void mlp1_kernel(const float* __restrict__ mw1) {
    __shared__ __align__(16) float sx[CK * 16];
    int cblk = blockIdx.x;
    int tid = threadIdx.x;
    int zid = cblk * 128 + tid;
    if (zid < NT) g_cursor[zid] = 0;
    int k0 = cblk * CK;
    const float4* gx4 = (const float4*)(g_x2t + k0 * 16);
    float4* sx4 = (float4*)sx;
    #pragma unroll
    for (int i = 0; i < 5; i++)
        sx4[tid + i * 128] = gx4[tid + i * 128];
    __syncthreads();
    int j = tid;
    float2 acc[8];
    #pragma unroll
    for (int p = 0; p < 8; p++) acc[p] = make_float2(0.f, 0.f);
    #pragma unroll 2
    for (int k = 0; k < CK; k++) {
        float wv = mw1[(k0 + k) * HIDn + j];
        float2 w2v = make_float2(wv, wv);
        float4 x0 = sx4[k * 4 + 0];
        float4 x1 = sx4[k * 4 + 1];
        float4 x2 = sx4[k * 4 + 2];
        float4 x3 = sx4[k * 4 + 3];
        acc[0] = ffma2(make_float2(x0.x, x0.y), w2v, acc[0]);
        acc[1] = ffma2(make_float2(x0.z, x0.w), w2v, acc[1]);
        acc[2] = ffma2(make_float2(x1.x, x1.y), w2v, acc[2]);
        acc[3] = ffma2(make_float2(x1.z, x1.w), w2v, acc[3]);
        acc[4] = ffma2(make_float2(x2.x, x2.y), w2v, acc[4]);
        acc[5] = ffma2(make_float2(x2.z, x2.w), w2v, acc[5]);
        acc[6] = ffma2(make_float2(x3.x, x3.y), w2v, acc[6]);
        acc[7] = ffma2(make_float2(x3.z, x3.w), w2v, acc[7]);
    }
    #pragma unroll
    for (int p = 0; p < 8; p++) {
        g_part[(cblk * 16 + 2 * p) * HIDn + j]     = acc[p].x;
        g_part[(cblk * 16 + 2 * p + 1) * HIDn + j] = acc[p].y;
    }
}

__global__ void reduce_kernel(const float* __restrict__ mb1) {
    int idx = blockIdx.x * 128 + threadIdx.x;
    if (idx >= 16 * HIDn) return;
    int b = idx >> 7, j = idx & 127;
    float s = 0.f;
    #pragma unroll 4
    for (int c = 0; c < NCHUNK; c++)
        s += g_part[(c * 16 + b) * HIDn + j];
    s += mb1[j];
    g_y1[b * HIDn + j] = fmaxf(s, 0.f);
}

// ================= tail: mlp2 (redundant per block) + output head =================
__global__ __launch_bounds__(256) void tail_kernel(
    const float* __restrict__ mw2, const float* __restrict__ mb2,
    const float* __restrict__ ow,  const float* __restrict__ ob,
    float* __restrict__ out)
{
    __shared__ float y1s[16 * HIDn];
    __shared__ float y2s[16 * HIDn];
    int tid = threadIdx.x;
    int bid = blockIdx.x;
    for (int i = tid; i < 16 * HIDn; i += 256) y1s[i] = g_y1[i];
    __syncthreads();
    if (tid < 128) {
        int j = tid;
        float acc[16];
        #pragma unroll
        for (int b = 0; b < 16; b++) acc[b] = 0.f;
        #pragma unroll 4
        for (int k = 0; k < HIDn; k++) {
            float wv = mw2[k * HIDn + j];
            #pragma unroll
            for (int b = 0; b < 16; b++)
                acc[b] = fmaf(y1s[b * HIDn + k], wv, acc[b]);
        }
        #pragma unroll
        for (int b = 0; b < 16; b++)
            y2s[b * HIDn + j] = fmaxf(acc[b] + mb2[j], 0.f);
    }
    __syncthreads();
    int j = bid * 128 + (tid & 127);
    int bh = tid >> 7;
    if (j < Nn) {
        float acc[8];
        #pragma unroll
        for (int b = 0; b < 8; b++) acc[b] = 0.f;
        const float* y = y2s + bh * 8 * HIDn;
        #pragma unroll 4
        for (int k = 0; k < HIDn; k++) {
            float wv = ow[k * Nn + j];
            #pragma unroll
            for (int b = 0; b < 8; b++)
                acc[b] = fmaf(y[b * HIDn + k], wv, acc[b]);
        }
        float obj = ob[j];
        #pragma unroll
        for (int b = 0; b < 8; b++) {
            float v = acc[b] + obj;
            out[(bh * 8 + b) * Nn + j] = 1.0f / (1.0f + __expf(-v));
        }
    }
}

// ------------------------- launch -------------------------
extern "C" void kernel_launch(void* const* d_in, const int* in_sizes, int n_in,
                              void* d_out, int out_size) {
    const float* actions = (const float*)d_in[0];
    const float* nodef   = (const float*)d_in[1];
    const int*   ei      = (const int*)d_in[2];
    const float* W1  = (const float*)d_in[3];
    const float* as1 = (const float*)d_in[4];
    const float* ad1 = (const float*)d_in[5];
    const float* b1  = (const float*)d_in[6];
    const float* W2  = (const float*)d_in[7];
    const float* as2 = (const float*)d_in[8];
    const float* ad2 = (const float*)d_in[9];
    const float* b2  = (const float*)d_in[10];
    const float* mw1 = (const float*)d_in[11];
    const float* mb1 = (const float*)d_in[12];
    const float* mw2 = (const float*)d_in[13];
    const float* mb2 = (const float*)d_in[14];
    const float* ow  = (const float*)d_in[15];
    const float* ob  = (const float*)d_in[16];
    float* out = (float*)d_out;

    cudaFuncSetAttribute(fgemm_kernel, cudaFuncAttributeMaxDynamicSharedMemorySize, FS_TOTAL);

    build_kernel<<<330, 256>>>(actions, nodef, W1, as1, ad1, ei);
    conv1_kernel<<<282, 256>>>();
    fgemm_kernel<<<250, 256, FS_TOTAL>>>(W1, b1, W2, as2, ad2);
    conv2_kernel<<<1000, 256>>>(b2);
    mlp1_kernel<<<NCHUNK, 128>>>(mw1);
    reduce_kernel<<<16, 128>>>(mb1);
    tail_kernel<<<8, 256>>>(mw2, mb2, ow, ob, out);
}

// round 16
// speedup vs baseline: 1.2157x; 1.2157x over previous
#include <cuda_runtime.h>
#include <math.h>
#include <stdint.h>

#define Bn 16
#define Nn 1000
#define En 16000
#define NT 16000
#define EBASE 256000
#define ETOT 272000
#define TWOE 32000
#define HALFB 8
#define NLOW 8000         /* dsts 0..7999 have only their self loop (structural) */

#define H1n 8
#define F1 1024
#define EMBn 64
#define HIDn 128
#define BCAP 96

#define NCHUNK 400
#define CK 160

// ------------------------- scratch -------------------------
__device__ __align__(16) float4 g_xf[NT];
__device__ float g_psrc[24];
__device__ float g_pdst[24];
__device__ int   g_cursor[NT];                 // zero at load; re-zeroed in mlp1
__device__ int   g_bucket[NT * BCAP];
__device__ __align__(16) float g_s[NT * 24];
__device__ __align__(16) float g_h2[NT * EMBn];
__device__ float g_a2s[NT];
__device__ float g_a2d[NT];
__device__ __align__(16) float g_x2t[64000 * 16];
__device__ float g_part[NCHUNK * 16 * HIDn];
__device__ float g_y1[16 * HIDn];

// ------------------------- helpers -------------------------
__device__ __forceinline__ void edge_sd(int e, const int* __restrict__ EI, int& src, int& dst) {
    if (e < EBASE) {
        int b   = e / TWOE;
        int rem = e - b * TWOE;
        src = EI[b * TWOE + rem] + b * Nn;
        int b2 = b + HALFB;
        dst = EI[b2 * TWOE + rem] + b2 * Nn;
    } else {
        src = dst = e - EBASE;
    }
}

__device__ __forceinline__ float warp_sum(float v) {
    #pragma unroll
    for (int o = 16; o > 0; o >>= 1) v += __shfl_xor_sync(0xffffffffu, v, o);
    return v;
}
__device__ __forceinline__ float leaky(float v) { return v > 0.f ? v : 0.2f * v; }
__device__ __forceinline__ float elu(float v)   { return v > 0.f ? v : (__expf(v) - 1.0f); }

__device__ __forceinline__ float2 ffma2(float2 a, float2 b, float2 c) {
    unsigned long long A = *reinterpret_cast<unsigned long long*>(&a);
    unsigned long long B = *reinterpret_cast<unsigned long long*>(&b);
    unsigned long long C = *reinterpret_cast<unsigned long long*>(&c);
    unsigned long long D;
    asm("fma.rn.f32x2 %0, %1, %2, %3;" : "=l"(D) : "l"(A), "l"(B), "l"(C));
    return *reinterpret_cast<float2*>(&D);
}

// pack two floats to bf16x2: first arg -> LOW 16 bits, second -> HIGH
__device__ __forceinline__ uint32_t pk(float lo, float hi) {
    uint32_t r;
    asm("cvt.rn.bf16x2.f32 %0, %1, %2;" : "=r"(r) : "f"(hi), "f"(lo));
    return r;
}
__device__ __forceinline__ float lo16f(uint32_t p) { return __uint_as_float(p << 16); }
__device__ __forceinline__ float hi16f(uint32_t p) { return __uint_as_float(p & 0xffff0000u); }

#define MMA_B16(dj, A0, A1, A2, A3, B0, B1)                                              \
    asm volatile("mma.sync.aligned.m16n8k16.row.col.f32.bf16.bf16.f32 "                  \
                 "{%0,%1,%2,%3}, {%4,%5,%6,%7}, {%8,%9}, {%0,%1,%2,%3};"                 \
                 : "+f"(dj[0]), "+f"(dj[1]), "+f"(dj[2]), "+f"(dj[3])                    \
                 : "r"(A0), "r"(A1), "r"(A2), "r"(A3), "r"(B0), "r"(B1))

// ================= build: node features + projections + bucket scatter =================
__global__ void build_kernel(const float* __restrict__ actions,
                             const float* __restrict__ nodef,
                             const float* __restrict__ W1,
                             const float* __restrict__ as1,
                             const float* __restrict__ ad1,
                             const int* __restrict__ EI) {
    int blk = blockIdx.x;
    if (blk < 63) {
        int n = blk * 256 + threadIdx.x;
        if (n >= NT) return;
        float ax = actions[n * 2 + 0];
        float ay = actions[n * 2 + 1];
        float nf = nodef[n];
        g_xf[n] = make_float4(ax, ay, nf, 0.f);
    } else if (blk == 63) {
        int t = threadIdx.x;
        if (t < 48) {
            int which = t / 24;
            int r = t % 24;
            int k = r / 8, h = r % 8;
            const float* att = which ? ad1 : as1;
            float s = 0.f;
            for (int c = 0; c < 128; c++)
                s += W1[k * F1 + h * 128 + c] * att[h * 128 + c];
            (which ? g_pdst : g_psrc)[k * 8 + h] = s;
        }
    } else {
        int idx = (blk - 64) * 256 + threadIdx.x;
        #pragma unroll
        for (int q = 0; q < 4; q++) {
            int e = idx * 4 + q;
            if (e < ETOT) {
                int src, dst;
                edge_sd(e, EI, src, dst);
                if (dst >= NLOW) {
                    int pos = atomicAdd(&g_cursor[dst], 1);
                    g_bucket[dst * BCAP + pos] = src;
                }
            }
        }
    }
}

// ================= conv1: thread per (dst, head); low half = identity =================
__global__ __launch_bounds__(256) void conv1_kernel() {
    int gidx = blockIdx.x * 256 + threadIdx.x;
    if (gidx < 8000) {
        int d = gidx;
        float4 x = g_xf[d];
        float4 v0 = make_float4(x.x, x.y, x.z, x.x);
        float4 v1 = make_float4(x.y, x.z, x.x, x.y);
        float4 v2 = make_float4(x.z, x.x, x.y, x.z);
        float4* sp = (float4*)(g_s + d * 24);
        sp[0] = v0; sp[1] = v1; sp[2] = v2;
        sp[3] = v0; sp[4] = v1; sp[5] = v2;
    } else if (gidx < 8000 + 64000) {
        int i2 = gidx - 8000;
        int d = NLOW + (i2 >> 3), h = i2 & 7;
        float4 xd = g_xf[d];
        float p0 = g_psrc[h], p1 = g_psrc[8 + h], p2 = g_psrc[16 + h];
        float q0 = g_pdst[h], q1 = g_pdst[8 + h], q2 = g_pdst[16 + h];
        float adv = fmaf(xd.x, q0, fmaf(xd.y, q1, xd.z * q2));
        int deg = g_cursor[d];
        const int* bkt = g_bucket + d * BCAP;
        float se = 0.f, sx = 0.f, sy = 0.f, sz = 0.f;
        for (int e = 0; e < deg; e++) {
            int s = bkt[e];
            float4 x = g_xf[s];
            float a = fmaf(x.x, p0, fmaf(x.y, p1, x.z * p2)) + adv;
            float ea = __expf(leaky(a));
            se += ea;
            sx = fmaf(ea, x.x, sx);
            sy = fmaf(ea, x.y, sy);
            sz = fmaf(ea, x.z, sz);
        }
        float inv = 1.0f / se;
        float* sp = g_s + d * 24 + h * 3;
        sp[0] = sx * inv; sp[1] = sy * inv; sp[2] = sz * inv;
    }
}

// ================= fgemm: mma.sync split-bf16  h2 = elu(s@W1+b1) @ W2  + attn2 =================
// 250 blocks x 256 threads (8 warps), 2 CTAs/SM. Block = 64 rows x 64 cols, K=1024.
// Warp: rows (wid&3)*16, cols (wid>>2)*32 (4 n8-tiles). A built in-register in frag layout.
#define FS_W1T 0                          /* 16384: {W1r0,W1r1,W1r2,b1} per k */
#define FS_W2C 16384                      /* 128*68*4 = 34816, padded chunk */
#define FS_SS  (FS_W2C + 34816)           /* 64*24*4 = 6144 */
#define FS_ATT (FS_SS + 6144)             /* 512 */
#define FS_TOTAL (FS_ATT + 512)

__global__ __launch_bounds__(256, 2) void fgemm_kernel(
    const float* __restrict__ W1, const float* __restrict__ b1,
    const float* __restrict__ W2, const float* __restrict__ as2,
    const float* __restrict__ ad2)
{
    extern __shared__ __align__(16) char dsm[];
    float4* w1t = (float4*)(dsm + FS_W1T);
    float*  w2c = (float*)(dsm + FS_W2C);     // [128][68]
    float*  sS  = (float*)(dsm + FS_SS);
    float*  att = (float*)(dsm + FS_ATT);

    int tid = threadIdx.x, bid = blockIdx.x;
    int wid = tid >> 5, lane = tid & 31;
    int g = lane >> 2, tg = lane & 3;
    int rbase = (wid & 3) * 16;
    int cbase = (wid >> 2) * 32;
    int row0 = bid * 64;

    for (int k = tid; k < F1; k += 256)
        w1t[k] = make_float4(W1[k], W1[F1 + k], W1[2 * F1 + k], b1[k]);
    for (int i = tid; i < 64 * 24; i += 256)
        sS[i] = g_s[row0 * 24 + i];
    if (tid < 128) att[tid] = (tid < 64) ? as2[tid] : ad2[tid - 64];

    float d[4][4];
    #pragma unroll
    for (int j = 0; j < 4; j++)
        #pragma unroll
        for (int q = 0; q < 4; q++) d[j][q] = 0.f;

    int ra = rbase + g, rb = ra + 8;

    for (int ch = 0; ch < 8; ch++) {
        __syncthreads();
        for (int i = tid; i < 128 * 64; i += 256) {
            int k = i >> 6, n = i & 63;
            w2c[k * 68 + n] = W2[(ch * 128 + k) * 64 + n];
        }
        __syncthreads();
        float sa0 = sS[ra * 24 + ch * 3 + 0];
        float sa1 = sS[ra * 24 + ch * 3 + 1];
        float sa2 = sS[ra * 24 + ch * 3 + 2];
        float sb0 = sS[rb * 24 + ch * 3 + 0];
        float sb1 = sS[rb * 24 + ch * 3 + 1];
        float sb2 = sS[rb * 24 + ch * 3 + 2];

        #pragma unroll 2
        for (int s = 0; s < 8; s++) {
            int k0 = ch * 128 + s * 16;
            // ---- A fragments (fused expand + elu, split bf16) ----
            float4 wA = w1t[k0 + 2 * tg];
            float4 wB = w1t[k0 + 2 * tg + 1];
            float4 wC = w1t[k0 + 2 * tg + 8];
            float4 wD = w1t[k0 + 2 * tg + 9];
            float zAa = elu(fmaf(sa0, wA.x, fmaf(sa1, wA.y, fmaf(sa2, wA.z, wA.w))));
            float zBa = elu(fmaf(sa0, wB.x, fmaf(sa1, wB.y, fmaf(sa2, wB.z, wB.w))));
            float zCa = elu(fmaf(sa0, wC.x, fmaf(sa1, wC.y, fmaf(sa2, wC.z, wC.w))));
            float zDa = elu(fmaf(sa0, wD.x, fmaf(sa1, wD.y, fmaf(sa2, wD.z, wD.w))));
            float zAb = elu(fmaf(sb0, wA.x, fmaf(sb1, wA.y, fmaf(sb2, wA.z, wA.w))));
            float zBb = elu(fmaf(sb0, wB.x, fmaf(sb1, wB.y, fmaf(sb2, wB.z, wB.w))));
            float zCb = elu(fmaf(sb0, wC.x, fmaf(sb1, wC.y, fmaf(sb2, wC.z, wC.w))));
            float zDb = elu(fmaf(sb0, wD.x, fmaf(sb1, wD.y, fmaf(sb2, wD.z, wD.w))));
            uint32_t ah0 = pk(zAa, zBa);
            uint32_t ah1 = pk(zAb, zBb);
            uint32_t ah2 = pk(zCa, zDa);
            uint32_t ah3 = pk(zCb, zDb);
            uint32_t al0 = pk(zAa - lo16f(ah0), zBa - hi16f(ah0));
            uint32_t al1 = pk(zAb - lo16f(ah1), zBb - hi16f(ah1));
            uint32_t al2 = pk(zCa - lo16f(ah2), zDa - hi16f(ah2));
            uint32_t al3 = pk(zCb - lo16f(ah3), zDb - hi16f(ah3));
            // ---- B fragments per n8-tile + 3 MMAs ----
            int ks = s * 16 + 2 * tg;
            #pragma unroll
            for (int j = 0; j < 4; j++) {
                int n = cbase + j * 8 + g;
                float v0 = w2c[ks * 68 + n];
                float v1 = w2c[(ks + 1) * 68 + n];
                float v8 = w2c[(ks + 8) * 68 + n];
                float v9 = w2c[(ks + 9) * 68 + n];
                uint32_t bh0 = pk(v0, v1);
                uint32_t bh1 = pk(v8, v9);
                uint32_t bl0 = pk(v0 - lo16f(bh0), v1 - hi16f(bh0));
                uint32_t bl1 = pk(v8 - lo16f(bh1), v9 - hi16f(bh1));
                MMA_B16(d[j], ah0, ah1, ah2, ah3, bh0, bh1);
                MMA_B16(d[j], ah0, ah1, ah2, ah3, bl0, bl1);
                MMA_B16(d[j], al0, al1, al2, al3, bh0, bh1);
            }
        }
    }
    __syncthreads();                       // w2c reads done; reuse as reduce scratch

    // store h2 + attn2 partials
    float ssa = 0.f, sda = 0.f, ssb = 0.f, sdb = 0.f;
    #pragma unroll
    for (int j = 0; j < 4; j++) {
        int c0 = cbase + j * 8 + 2 * tg;
        *(float2*)&g_h2[(row0 + ra) * EMBn + c0] = make_float2(d[j][0], d[j][1]);
        *(float2*)&g_h2[(row0 + rb) * EMBn + c0] = make_float2(d[j][2], d[j][3]);
        ssa += d[j][0] * att[c0] + d[j][1] * att[c0 + 1];
        sda += d[j][0] * att[64 + c0] + d[j][1] * att[64 + c0 + 1];
        ssb += d[j][2] * att[c0] + d[j][3] * att[c0 + 1];
        sdb += d[j][2] * att[64 + c0] + d[j][3] * att[64 + c0 + 1];
    }
    #pragma unroll
    for (int o = 1; o < 4; o <<= 1) {
        ssa += __shfl_xor_sync(0xffffffffu, ssa, o);
        sda += __shfl_xor_sync(0xffffffffu, sda, o);
        ssb += __shfl_xor_sync(0xffffffffu, ssb, o);
        sdb += __shfl_xor_sync(0xffffffffu, sdb, o);
    }
    float* red = w2c;                      // [2 halves][64 rows] ss, then sd at +256
    int half = wid >> 2;
    if (tg == 0) {
        red[half * 128 + rbase + g]           = ssa;
        red[half * 128 + rbase + g + 8]       = ssb;
        red[256 + half * 128 + rbase + g]     = sda;
        red[256 + half * 128 + rbase + g + 8] = sdb;
    }
    __syncthreads();
    if (tid < 64) {
        g_a2s[row0 + tid] = red[tid] + red[128 + tid];
        g_a2d[row0 + tid] = red[256 + tid] + red[256 + 128 + tid];
    }
}

// ================= conv2: warp per heavy dst; low half elementwise =================
__global__ __launch_bounds__(256) void conv2_kernel(const float* __restrict__ b2) {
    __shared__ float wbuf[8][BCAP];
    __shared__ int   ibuf[8][BCAP];
    int tid = threadIdx.x;
    int gidx = blockIdx.x * 256 + tid;
    int lane = tid & 31;
    int w = tid >> 5;
    int wg = gidx >> 5;                         // 8000 warps
    {
        int d = NLOW + wg;
        int deg = g_cursor[d];
        const int* bkt = g_bucket + d * BCAP;
        float adv = g_a2d[d];
        float se = 0.f;
        for (int e = lane; e < deg; e += 32) {
            int src = bkt[e];
            float ea = __expf(leaky(g_a2s[src] + adv));
            wbuf[w][e] = ea;
            ibuf[w][e] = src;
            se += ea;
        }
        __syncwarp();
        float2 acc = make_float2(0.f, 0.f);
        #pragma unroll 4
        for (int e = 0; e < deg; e++) {
            float ea = wbuf[w][e];
            int src = ibuf[w][e];
            float2 v = ((const float2*)(g_h2 + src * 64))[lane];
            acc.x = fmaf(ea, v.x, acc.x);
            acc.y = fmaf(ea, v.y, acc.y);
        }
        __syncwarp();
        se = warp_sum(se);
        float inv = 1.0f / se;
        float2 bb = ((const float2*)b2)[lane];
        int b = d / Nn, n = d - b * Nn;
        int c = lane * 2;
        g_x2t[(n * 64 + c) * 16 + b]     = elu(acc.x * inv + bb.x);
        g_x2t[(n * 64 + c + 1) * 16 + b] = elu(acc.y * inv + bb.y);
    }
    {   // low half: 8000*32 threads exactly
        int d = gidx >> 5, ln = gidx & 31;
        float2 v = ((const float2*)(g_h2 + d * 64))[ln];
        float2 bb = ((const float2*)b2)[ln];
        int b = d / Nn, n = d - b * Nn;
        int c = ln * 2;
        g_x2t[(n * 64 + c) * 16 + b]     = elu(v.x + bb.x);
        g_x2t[(n * 64 + c + 1) * 16 + b] = elu(v.y + bb.y);
    }
}

// ================= mlp1 split-K stage 1 (+ cursor reset) =================
__global__ __launch_bounds__(128) void mlp1_kernel(const float* __restrict__ mw1) {
    __shared__ __align__(16) float sx[CK * 16];
    int cblk = blockIdx.x;
    int tid = threadIdx.x;
    int zid = cblk * 128 + tid;
    if (zid < NT) g_cursor[zid] = 0;
    int k0 = cblk * CK;
    const float4* gx4 = (const float4*)(g_x2t + k0 * 16);
    float4* sx4 = (float4*)sx;
    #pragma unroll
    for (int i = 0; i < 5; i++)
        sx4[tid + i * 128] = gx4[tid + i * 128];
    __syncthreads();
    int j = tid;
    float2 acc[8];
    #pragma unroll
    for (int p = 0; p < 8; p++) acc[p] = make_float2(0.f, 0.f);
    #pragma unroll 2
    for (int k = 0; k < CK; k++) {
        float wv = mw1[(k0 + k) * HIDn + j];
        float2 w2v = make_float2(wv, wv);
        float4 x0 = sx4[k * 4 + 0];
        float4 x1 = sx4[k * 4 + 1];
        float4 x2 = sx4[k * 4 + 2];
        float4 x3 = sx4[k * 4 + 3];
        acc[0] = ffma2(make_float2(x0.x, x0.y), w2v, acc[0]);
        acc[1] = ffma2(make_float2(x0.z, x0.w), w2v, acc[1]);
        acc[2] = ffma2(make_float2(x1.x, x1.y), w2v, acc[2]);
        acc[3] = ffma2(make_float2(x1.z, x1.w), w2v, acc[3]);
        acc[4] = ffma2(make_float2(x2.x, x2.y), w2v, acc[4]);
        acc[5] = ffma2(make_float2(x2.z, x2.w), w2v, acc[5]);
        acc[6] = ffma2(make_float2(x3.x, x3.y), w2v, acc[6]);
        acc[7] = ffma2(make_float2(x3.z, x3.w), w2v, acc[7]);
    }
    #pragma unroll
    for (int p = 0; p < 8; p++) {
        g_part[(cblk * 16 + 2 * p) * HIDn + j]     = acc[p].x;
        g_part[(cblk * 16 + 2 * p + 1) * HIDn + j] = acc[p].y;
    }
}

__global__ void reduce_kernel(const float* __restrict__ mb1) {
    int idx = blockIdx.x * 128 + threadIdx.x;
    if (idx >= 16 * HIDn) return;
    int b = idx >> 7, j = idx & 127;
    float s = 0.f;
    #pragma unroll 4
    for (int c = 0; c < NCHUNK; c++)
        s += g_part[(c * 16 + b) * HIDn + j];
    s += mb1[j];
    g_y1[b * HIDn + j] = fmaxf(s, 0.f);
}

// ================= tail: mlp2 (redundant per block) + output head =================
__global__ __launch_bounds__(256) void tail_kernel(
    const float* __restrict__ mw2, const float* __restrict__ mb2,
    const float* __restrict__ ow,  const float* __restrict__ ob,
    float* __restrict__ out)
{
    __shared__ float y1s[16 * HIDn];
    __shared__ float y2s[16 * HIDn];
    int tid = threadIdx.x;
    int bid = blockIdx.x;
    for (int i = tid; i < 16 * HIDn; i += 256) y1s[i] = g_y1[i];
    __syncthreads();
    if (tid < 128) {
        int j = tid;
        float acc[16];
        #pragma unroll
        for (int b = 0; b < 16; b++) acc[b] = 0.f;
        #pragma unroll 4
        for (int k = 0; k < HIDn; k++) {
            float wv = mw2[k * HIDn + j];
            #pragma unroll
            for (int b = 0; b < 16; b++)
                acc[b] = fmaf(y1s[b * HIDn + k], wv, acc[b]);
        }
        #pragma unroll
        for (int b = 0; b < 16; b++)
            y2s[b * HIDn + j] = fmaxf(acc[b] + mb2[j], 0.f);
    }
    __syncthreads();
    int j = bid * 128 + (tid & 127);
    int bh = tid >> 7;
    if (j < Nn) {
        float acc[8];
        #pragma unroll
        for (int b = 0; b < 8; b++) acc[b] = 0.f;
        const float* y = y2s + bh * 8 * HIDn;
        #pragma unroll 4
        for (int k = 0; k < HIDn; k++) {
            float wv = ow[k * Nn + j];
            #pragma unroll
            for (int b = 0; b < 8; b++)
                acc[b] = fmaf(y[b * HIDn + k], wv, acc[b]);
        }
        float obj = ob[j];
        #pragma unroll
        for (int b = 0; b < 8; b++) {
            float v = acc[b] + obj;
            out[(bh * 8 + b) * Nn + j] = 1.0f / (1.0f + __expf(-v));
        }
    }
}

// ------------------------- launch -------------------------
extern "C" void kernel_launch(void* const* d_in, const int* in_sizes, int n_in,
                              void* d_out, int out_size) {
    const float* actions = (const float*)d_in[0];
    const float* nodef   = (const float*)d_in[1];
    const int*   ei      = (const int*)d_in[2];
    const float* W1  = (const float*)d_in[3];
    const float* as1 = (const float*)d_in[4];
    const float* ad1 = (const float*)d_in[5];
    const float* b1  = (const float*)d_in[6];
    const float* W2  = (const float*)d_in[7];
    const float* as2 = (const float*)d_in[8];
    const float* ad2 = (const float*)d_in[9];
    const float* b2  = (const float*)d_in[10];
    const float* mw1 = (const float*)d_in[11];
    const float* mb1 = (const float*)d_in[12];
    const float* mw2 = (const float*)d_in[13];
    const float* mb2 = (const float*)d_in[14];
    const float* ow  = (const float*)d_in[15];
    const float* ob  = (const float*)d_in[16];
    float* out = (float*)d_out;

    cudaFuncSetAttribute(fgemm_kernel, cudaFuncAttributeMaxDynamicSharedMemorySize, FS_TOTAL);

    build_kernel<<<330, 256>>>(actions, nodef, W1, as1, ad1, ei);
    conv1_kernel<<<282, 256>>>();
    fgemm_kernel<<<250, 256, FS_TOTAL>>>(W1, b1, W2, as2, ad2);
    conv2_kernel<<<1000, 256>>>(b2);
    mlp1_kernel<<<NCHUNK, 128>>>(mw1);
    reduce_kernel<<<16, 128>>>(mb1);
    tail_kernel<<<8, 256>>>(mw2, mb2, ow, ob, out);
}

// round 17
// speedup vs baseline: 1.3451x; 1.1064x over previous
#include <cuda_runtime.h>
#include <math.h>
#include <stdint.h>

#define Bn 16
#define Nn 1000
#define En 16000
#define NT 16000
#define EBASE 256000
#define ETOT 272000
#define TWOE 32000
#define HALFB 8
#define NLOW 8000         /* dsts 0..7999 have only their self loop (structural) */

#define H1n 8
#define F1 1024
#define EMBn 64
#define HIDn 128
#define BCAP 96

#define NCHUNK 400
#define CK 160

// ------------------------- scratch -------------------------
__device__ __align__(16) float4 g_xf[NT];
__device__ float g_psrc[24];
__device__ float g_pdst[24];
__device__ int   g_cursor[NT];                 // zero at load; re-zeroed in mlp1
__device__ int   g_bucket[NT * BCAP];
__device__ __align__(16) float g_s[NT * 24];
__device__ __align__(16) float g_h2[NT * EMBn];
__device__ float g_a2s[NT];
__device__ float g_a2d[NT];
__device__ __align__(16) float g_x2t[64000 * 16];
__device__ float g_part[NCHUNK * 16 * HIDn];
__device__ float g_y1[16 * HIDn];
__device__ __align__(16) uint4 g_w2f[64 * 8 * 32];   // W2 split-bf16 mma fragments (512 KB)

// ------------------------- helpers -------------------------
__device__ __forceinline__ void edge_sd(int e, const int* __restrict__ EI, int& src, int& dst) {
    if (e < EBASE) {
        int b   = e / TWOE;
        int rem = e - b * TWOE;
        src = EI[b * TWOE + rem] + b * Nn;
        int b2 = b + HALFB;
        dst = EI[b2 * TWOE + rem] + b2 * Nn;
    } else {
        src = dst = e - EBASE;
    }
}

__device__ __forceinline__ float warp_sum(float v) {
    #pragma unroll
    for (int o = 16; o > 0; o >>= 1) v += __shfl_xor_sync(0xffffffffu, v, o);
    return v;
}
__device__ __forceinline__ float leaky(float v) { return v > 0.f ? v : 0.2f * v; }
__device__ __forceinline__ float elu(float v)   { return v > 0.f ? v : (__expf(v) - 1.0f); }

__device__ __forceinline__ float2 ffma2(float2 a, float2 b, float2 c) {
    unsigned long long A = *reinterpret_cast<unsigned long long*>(&a);
    unsigned long long B = *reinterpret_cast<unsigned long long*>(&b);
    unsigned long long C = *reinterpret_cast<unsigned long long*>(&c);
    unsigned long long D;
    asm("fma.rn.f32x2 %0, %1, %2, %3;" : "=l"(D) : "l"(A), "l"(B), "l"(C));
    return *reinterpret_cast<float2*>(&D);
}

// pack two floats to bf16x2: first arg -> LOW 16 bits, second -> HIGH
__device__ __forceinline__ uint32_t pk(float lo, float hi) {
    uint32_t r;
    asm("cvt.rn.bf16x2.f32 %0, %1, %2;" : "=r"(r) : "f"(hi), "f"(lo));
    return r;
}
__device__ __forceinline__ float lo16f(uint32_t p) { return __uint_as_float(p << 16); }
__device__ __forceinline__ float hi16f(uint32_t p) { return __uint_as_float(p & 0xffff0000u); }

#define MMA_B16(dj, A0, A1, A2, A3, B0, B1)                                              \
    asm volatile("mma.sync.aligned.m16n8k16.row.col.f32.bf16.bf16.f32 "                  \
                 "{%0,%1,%2,%3}, {%4,%5,%6,%7}, {%8,%9}, {%0,%1,%2,%3};"                 \
                 : "+f"(dj[0]), "+f"(dj[1]), "+f"(dj[2]), "+f"(dj[3])                    \
                 : "r"(A0), "r"(A1), "r"(A2), "r"(A3), "r"(B0), "r"(B1))

// ================= build: node features + projections + scatter + W2 fragments =================
__global__ void build_kernel(const float* __restrict__ actions,
                             const float* __restrict__ nodef,
                             const float* __restrict__ W1,
                             const float* __restrict__ as1,
                             const float* __restrict__ ad1,
                             const int* __restrict__ EI,
                             const float* __restrict__ W2) {
    int blk = blockIdx.x;
    if (blk < 63) {
        int n = blk * 256 + threadIdx.x;
        if (n >= NT) return;
        float ax = actions[n * 2 + 0];
        float ay = actions[n * 2 + 1];
        float nf = nodef[n];
        g_xf[n] = make_float4(ax, ay, nf, 0.f);
    } else if (blk == 63) {
        int t = threadIdx.x;
        if (t < 48) {
            int which = t / 24;
            int r = t % 24;
            int k = r / 8, h = r % 8;
            const float* att = which ? ad1 : as1;
            float s = 0.f;
            for (int c = 0; c < 128; c++)
                s += W1[k * F1 + h * 128 + c] * att[h * 128 + c];
            (which ? g_pdst : g_psrc)[k * 8 + h] = s;
        }
    } else if (blk < 330) {
        int idx = (blk - 64) * 256 + threadIdx.x;
        #pragma unroll
        for (int q = 0; q < 4; q++) {
            int e = idx * 4 + q;
            if (e < ETOT) {
                int src, dst;
                edge_sd(e, EI, src, dst);
                if (dst >= NLOW) {
                    int pos = atomicAdd(&g_cursor[dst], 1);
                    g_bucket[dst * BCAP + pos] = src;
                }
            }
        }
    } else {
        // W2 split-bf16 fragment table: idx = s*256 + jj*32 + lane
        int idx = (blk - 330) * 256 + threadIdx.x;     // 64 blocks -> 16384 entries
        int s = idx >> 8;
        int rem = idx & 255;
        int jj = rem >> 5;
        int lane = rem & 31;
        int g = lane >> 2, tg = lane & 3;
        int n = jj * 8 + g;
        int ks = s * 16 + 2 * tg;
        float v0 = W2[ks * 64 + n];
        float v1 = W2[(ks + 1) * 64 + n];
        float v8 = W2[(ks + 8) * 64 + n];
        float v9 = W2[(ks + 9) * 64 + n];
        uint32_t bh0 = pk(v0, v1);
        uint32_t bh1 = pk(v8, v9);
        uint32_t bl0 = pk(v0 - lo16f(bh0), v1 - hi16f(bh0));
        uint32_t bl1 = pk(v8 - lo16f(bh1), v9 - hi16f(bh1));
        g_w2f[idx] = make_uint4(bh0, bh1, bl0, bl1);
    }
}

// ================= conv1: thread per (dst, head); low half = identity; 2-edge ILP =================
__global__ __launch_bounds__(256) void conv1_kernel() {
    int gidx = blockIdx.x * 256 + threadIdx.x;
    if (gidx < 8000) {
        int d = gidx;
        float4 x = g_xf[d];
        float4 v0 = make_float4(x.x, x.y, x.z, x.x);
        float4 v1 = make_float4(x.y, x.z, x.x, x.y);
        float4 v2 = make_float4(x.z, x.x, x.y, x.z);
        float4* sp = (float4*)(g_s + d * 24);
        sp[0] = v0; sp[1] = v1; sp[2] = v2;
        sp[3] = v0; sp[4] = v1; sp[5] = v2;
    } else if (gidx < 8000 + 64000) {
        int i2 = gidx - 8000;
        int d = NLOW + (i2 >> 3), h = i2 & 7;
        float4 xd = g_xf[d];
        float p0 = g_psrc[h], p1 = g_psrc[8 + h], p2 = g_psrc[16 + h];
        float q0 = g_pdst[h], q1 = g_pdst[8 + h], q2 = g_pdst[16 + h];
        float adv = fmaf(xd.x, q0, fmaf(xd.y, q1, xd.z * q2));
        int deg = g_cursor[d];
        const int* bkt = g_bucket + d * BCAP;
        float se = 0.f, sx = 0.f, sy = 0.f, sz = 0.f;
        float se2 = 0.f, sx2 = 0.f, sy2 = 0.f, sz2 = 0.f;
        int e = 0;
        for (; e + 1 < deg; e += 2) {
            int s0i = bkt[e];
            int s1i = bkt[e + 1];
            float4 x0 = g_xf[s0i];
            float4 x1 = g_xf[s1i];
            float a0 = fmaf(x0.x, p0, fmaf(x0.y, p1, x0.z * p2)) + adv;
            float a1 = fmaf(x1.x, p0, fmaf(x1.y, p1, x1.z * p2)) + adv;
            float ea0 = __expf(leaky(a0));
            float ea1 = __expf(leaky(a1));
            se += ea0;  sx = fmaf(ea0, x0.x, sx);  sy = fmaf(ea0, x0.y, sy);  sz = fmaf(ea0, x0.z, sz);
            se2 += ea1; sx2 = fmaf(ea1, x1.x, sx2); sy2 = fmaf(ea1, x1.y, sy2); sz2 = fmaf(ea1, x1.z, sz2);
        }
        if (e < deg) {
            int s0i = bkt[e];
            float4 x0 = g_xf[s0i];
            float a0 = fmaf(x0.x, p0, fmaf(x0.y, p1, x0.z * p2)) + adv;
            float ea0 = __expf(leaky(a0));
            se += ea0; sx = fmaf(ea0, x0.x, sx); sy = fmaf(ea0, x0.y, sy); sz = fmaf(ea0, x0.z, sz);
        }
        se += se2; sx += sx2; sy += sy2; sz += sz2;
        float inv = 1.0f / se;
        float* sp = g_s + d * 24 + h * 3;
        sp[0] = sx * inv; sp[1] = sy * inv; sp[2] = sz * inv;
    }
}

// ================= fgemm: mma.sync split-bf16 with precomputed B fragments =================
// 250 blocks x 256 threads (8 warps), 2 CTAs/SM. Block = 64 rows x 64 cols, K=1024.
#define FS_W1T 0                          /* 16384 */
#define FS_FRAG 16384                     /* 8 s x 8 jj x 32 lanes x 16B = 32768 */
#define FS_SS  (FS_FRAG + 32768)          /* 6144 */
#define FS_ATT (FS_SS + 6144)             /* 512 */
#define FS_TOTAL (FS_ATT + 512)

__global__ __launch_bounds__(256, 2) void fgemm_kernel(
    const float* __restrict__ W1, const float* __restrict__ b1,
    const float* __restrict__ as2, const float* __restrict__ ad2)
{
    extern __shared__ __align__(16) char dsm[];
    float4* w1t  = (float4*)(dsm + FS_W1T);
    uint4*  frag = (uint4*)(dsm + FS_FRAG);
    float*  sS   = (float*)(dsm + FS_SS);
    float*  att  = (float*)(dsm + FS_ATT);

    int tid = threadIdx.x, bid = blockIdx.x;
    int wid = tid >> 5, lane = tid & 31;
    int g = lane >> 2, tg = lane & 3;
    int rbase = (wid & 3) * 16;
    int cbase = (wid >> 2) * 32;
    int jbase = cbase >> 3;               // 0 or 4
    int row0 = bid * 64;

    for (int k = tid; k < F1; k += 256)
        w1t[k] = make_float4(W1[k], W1[F1 + k], W1[2 * F1 + k], b1[k]);
    for (int i = tid; i < 64 * 24; i += 256)
        sS[i] = g_s[row0 * 24 + i];
    if (tid < 128) att[tid] = (tid < 64) ? as2[tid] : ad2[tid - 64];

    float d[4][4];
    #pragma unroll
    for (int j = 0; j < 4; j++)
        #pragma unroll
        for (int q = 0; q < 4; q++) d[j][q] = 0.f;

    int ra = rbase + g, rb = ra + 8;

    for (int ch = 0; ch < 8; ch++) {
        __syncthreads();
        {   // stage fragment slice for this chunk: 2048 uint4
            const uint4* src = g_w2f + ch * 2048;
            #pragma unroll
            for (int i = 0; i < 8; i++)
                frag[tid + i * 256] = src[tid + i * 256];
        }
        __syncthreads();
        float sa0 = sS[ra * 24 + ch * 3 + 0];
        float sa1 = sS[ra * 24 + ch * 3 + 1];
        float sa2 = sS[ra * 24 + ch * 3 + 2];
        float sb0 = sS[rb * 24 + ch * 3 + 0];
        float sb1 = sS[rb * 24 + ch * 3 + 1];
        float sb2 = sS[rb * 24 + ch * 3 + 2];

        #pragma unroll 2
        for (int s = 0; s < 8; s++) {
            int k0 = ch * 128 + s * 16;
            // ---- A fragments (fused expand + elu, split bf16) ----
            float4 wA = w1t[k0 + 2 * tg];
            float4 wB = w1t[k0 + 2 * tg + 1];
            float4 wC = w1t[k0 + 2 * tg + 8];
            float4 wD = w1t[k0 + 2 * tg + 9];
            float zAa = elu(fmaf(sa0, wA.x, fmaf(sa1, wA.y, fmaf(sa2, wA.z, wA.w))));
            float zBa = elu(fmaf(sa0, wB.x, fmaf(sa1, wB.y, fmaf(sa2, wB.z, wB.w))));
            float zCa = elu(fmaf(sa0, wC.x, fmaf(sa1, wC.y, fmaf(sa2, wC.z, wC.w))));
            float zDa = elu(fmaf(sa0, wD.x, fmaf(sa1, wD.y, fmaf(sa2, wD.z, wD.w))));
            float zAb = elu(fmaf(sb0, wA.x, fmaf(sb1, wA.y, fmaf(sb2, wA.z, wA.w))));
            float zBb = elu(fmaf(sb0, wB.x, fmaf(sb1, wB.y, fmaf(sb2, wB.z, wB.w))));
            float zCb = elu(fmaf(sb0, wC.x, fmaf(sb1, wC.y, fmaf(sb2, wC.z, wC.w))));
            float zDb = elu(fmaf(sb0, wD.x, fmaf(sb1, wD.y, fmaf(sb2, wD.z, wD.w))));
            uint32_t ah0 = pk(zAa, zBa);
            uint32_t ah1 = pk(zAb, zBb);
            uint32_t ah2 = pk(zCa, zDa);
            uint32_t ah3 = pk(zCb, zDb);
            uint32_t al0 = pk(zAa - lo16f(ah0), zBa - hi16f(ah0));
            uint32_t al1 = pk(zAb - lo16f(ah1), zBb - hi16f(ah1));
            uint32_t al2 = pk(zCa - lo16f(ah2), zDa - hi16f(ah2));
            uint32_t al3 = pk(zCb - lo16f(ah3), zDb - hi16f(ah3));
            // ---- B fragments: one LDS.128 per n8-tile ----
            const uint4* fs = frag + s * 256 + jbase * 32 + lane;
            #pragma unroll
            for (int j = 0; j < 4; j++) {
                uint4 f = fs[j * 32];
                MMA_B16(d[j], ah0, ah1, ah2, ah3, f.x, f.y);
                MMA_B16(d[j], ah0, ah1, ah2, ah3, f.z, f.w);
                MMA_B16(d[j], al0, al1, al2, al3, f.x, f.y);
            }
        }
    }
    __syncthreads();                       // frag reads done; reuse as reduce scratch

    // store h2 + attn2 partials
    float ssa = 0.f, sda = 0.f, ssb = 0.f, sdb = 0.f;
    #pragma unroll
    for (int j = 0; j < 4; j++) {
        int c0 = cbase + j * 8 + 2 * tg;
        *(float2*)&g_h2[(row0 + ra) * EMBn + c0] = make_float2(d[j][0], d[j][1]);
        *(float2*)&g_h2[(row0 + rb) * EMBn + c0] = make_float2(d[j][2], d[j][3]);
        ssa += d[j][0] * att[c0] + d[j][1] * att[c0 + 1];
        sda += d[j][0] * att[64 + c0] + d[j][1] * att[64 + c0 + 1];
        ssb += d[j][2] * att[c0] + d[j][3] * att[c0 + 1];
        sdb += d[j][2] * att[64 + c0] + d[j][3] * att[64 + c0 + 1];
    }
    #pragma unroll
    for (int o = 1; o < 4; o <<= 1) {
        ssa += __shfl_xor_sync(0xffffffffu, ssa, o);
        sda += __shfl_xor_sync(0xffffffffu, sda, o);
        ssb += __shfl_xor_sync(0xffffffffu, ssb, o);
        sdb += __shfl_xor_sync(0xffffffffu, sdb, o);
    }
    float* red = (float*)frag;
    int half = wid >> 2;
    if (tg == 0) {
        red[half * 128 + rbase + g]           = ssa;
        red[half * 128 + rbase + g + 8]       = ssb;
        red[256 + half * 128 + rbase + g]     = sda;
        red[256 + half * 128 + rbase + g + 8] = sdb;
    }
    __syncthreads();
    if (tid < 64) {
        g_a2s[row0 + tid] = red[tid] + red[128 + tid];
        g_a2d[row0 + tid] = red[256 + tid] + red[256 + 128 + tid];
    }
}

// ================= conv2: warp per heavy dst; low half elementwise =================
__global__ __launch_bounds__(256) void conv2_kernel(const float* __restrict__ b2) {
    __shared__ float wbuf[8][BCAP];
    __shared__ int   ibuf[8][BCAP];
    int tid = threadIdx.x;
    int gidx = blockIdx.x * 256 + tid;
    int lane = tid & 31;
    int w = tid >> 5;
    int wg = gidx >> 5;                         // 8000 warps
    {
        int d = NLOW + wg;
        int deg = g_cursor[d];
        const int* bkt = g_bucket + d * BCAP;
        float adv = g_a2d[d];
        float se = 0.f;
        for (int e = lane; e < deg; e += 32) {
            int src = bkt[e];
            float ea = __expf(leaky(g_a2s[src] + adv));
            wbuf[w][e] = ea;
            ibuf[w][e] = src;
            se += ea;
        }
        __syncwarp();
        float2 acc = make_float2(0.f, 0.f);
        #pragma unroll 4
        for (int e = 0; e < deg; e++) {
            float ea = wbuf[w][e];
            int src = ibuf[w][e];
            float2 v = ((const float2*)(g_h2 + src * 64))[lane];
            acc.x = fmaf(ea, v.x, acc.x);
            acc.y = fmaf(ea, v.y, acc.y);
        }
        __syncwarp();
        se = warp_sum(se);
        float inv = 1.0f / se;
        float2 bb = ((const float2*)b2)[lane];
        int b = d / Nn, n = d - b * Nn;
        int c = lane * 2;
        g_x2t[(n * 64 + c) * 16 + b]     = elu(acc.x * inv + bb.x);
        g_x2t[(n * 64 + c + 1) * 16 + b] = elu(acc.y * inv + bb.y);
    }
    {   // low half: 8000*32 threads exactly
        int d = gidx >> 5, ln = gidx & 31;
        float2 v = ((const float2*)(g_h2 + d * 64))[ln];
        float2 bb = ((const float2*)b2)[ln];
        int b = d / Nn, n = d - b * Nn;
        int c = ln * 2;
        g_x2t[(n * 64 + c) * 16 + b]     = elu(v.x + bb.x);
        g_x2t[(n * 64 + c + 1) * 16 + b] = elu(v.y + bb.y);
    }
}

// ================= mlp1 split-K stage 1 (+ cursor reset) =================
__global__ __launch_bounds__(128) void mlp1_kernel(const float* __restrict__ mw1) {
    __shared__ __align__(16) float sx[CK * 16];
    int cblk = blockIdx.x;
    int tid = threadIdx.x;
    int zid = cblk * 128 + tid;
    if (zid < NT) g_cursor[zid] = 0;
    int k0 = cblk * CK;
    const float4* gx4 = (const float4*)(g_x2t + k0 * 16);
    float4* sx4 = (float4*)sx;
    #pragma unroll
    for (int i = 0; i < 5; i++)
        sx4[tid + i * 128] = gx4[tid + i * 128];
    __syncthreads();
    int j = tid;
    float2 acc[8];
    #pragma unroll
    for (int p = 0; p < 8; p++) acc[p] = make_float2(0.f, 0.f);
    #pragma unroll 2
    for (int k = 0; k < CK; k++) {
        float wv = mw1[(k0 + k) * HIDn + j];
        float2 w2v = make_float2(wv, wv);
        float4 x0 = sx4[k * 4 + 0];
        float4 x1 = sx4[k * 4 + 1];
        float4 x2 = sx4[k * 4 + 2];
        float4 x3 = sx4[k * 4 + 3];
        acc[0] = ffma2(make_float2(x0.x, x0.y), w2v, acc[0]);
        acc[1] = ffma2(make_float2(x0.z, x0.w), w2v, acc[1]);
        acc[2] = ffma2(make_float2(x1.x, x1.y), w2v, acc[2]);
        acc[3] = ffma2(make_float2(x1.z, x1.w), w2v, acc[3]);
        acc[4] = ffma2(make_float2(x2.x, x2.y), w2v, acc[4]);
        acc[5] = ffma2(make_float2(x2.z, x2.w), w2v, acc[5]);
        acc[6] = ffma2(make_float2(x3.x, x3.y), w2v, acc[6]);
        acc[7] = ffma2(make_float2(x3.z, x3.w), w2v, acc[7]);
    }
    #pragma unroll
    for (int p = 0; p < 8; p++) {
        g_part[(cblk * 16 + 2 * p) * HIDn + j]     = acc[p].x;
        g_part[(cblk * 16 + 2 * p + 1) * HIDn + j] = acc[p].y;
    }
}

__global__ void reduce_kernel(const float* __restrict__ mb1) {
    int idx = blockIdx.x * 128 + threadIdx.x;
    if (idx >= 16 * HIDn) return;
    int b = idx >> 7, j = idx & 127;
    float s = 0.f;
    #pragma unroll 4
    for (int c = 0; c < NCHUNK; c++)
        s += g_part[(c * 16 + b) * HIDn + j];
    s += mb1[j];
    g_y1[b * HIDn + j] = fmaxf(s, 0.f);
}

// ================= tail: mlp2 (redundant per block) + output head =================
__global__ __launch_bounds__(256) void tail_kernel(
    const float* __restrict__ mw2, const float* __restrict__ mb2,
    const float* __restrict__ ow,  const float* __restrict__ ob,
    float* __restrict__ out)
{
    __shared__ float y1s[16 * HIDn];
    __shared__ float y2s[16 * HIDn];
    int tid = threadIdx.x;
    int bid = blockIdx.x;
    for (int i = tid; i < 16 * HIDn; i += 256) y1s[i] = g_y1[i];
    __syncthreads();
    if (tid < 128) {
        int j = tid;
        float acc[16];
        #pragma unroll
        for (int b = 0; b < 16; b++) acc[b] = 0.f;
        #pragma unroll 4
        for (int k = 0; k < HIDn; k++) {
            float wv = mw2[k * HIDn + j];
            #pragma unroll
            for (int b = 0; b < 16; b++)
                acc[b] = fmaf(y1s[b * HIDn + k], wv, acc[b]);
        }
        #pragma unroll
        for (int b = 0; b < 16; b++)
            y2s[b * HIDn + j] = fmaxf(acc[b] + mb2[j], 0.f);
    }
    __syncthreads();
    int j = bid * 128 + (tid & 127);
    int bh = tid >> 7;
    if (j < Nn) {
        float acc[8];
        #pragma unroll
        for (int b = 0; b < 8; b++) acc[b] = 0.f;
        const float* y = y2s + bh * 8 * HIDn;
        #pragma unroll 4
        for (int k = 0; k < HIDn; k++) {
            float wv = ow[k * Nn + j];
            #pragma unroll
            for (int b = 0; b < 8; b++)
                acc[b] = fmaf(y[b * HIDn + k], wv, acc[b]);
        }
        float obj = ob[j];
        #pragma unroll
        for (int b = 0; b < 8; b++) {
            float v = acc[b] + obj;
            out[(bh * 8 + b) * Nn + j] = 1.0f / (1.0f + __expf(-v));
        }
    }
}

// ------------------------- launch -------------------------
extern "C" void kernel_launch(void* const* d_in, const int* in_sizes, int n_in,
                              void* d_out, int out_size) {
    const float* actions = (const float*)d_in[0];
    const float* nodef   = (const float*)d_in[1];
    const int*   ei      = (const int*)d_in[2];
    const float* W1  = (const float*)d_in[3];
    const float* as1 = (const float*)d_in[4];
    const float* ad1 = (const float*)d_in[5];
    const float* b1  = (const float*)d_in[6];
    const float* W2  = (const float*)d_in[7];
    const float* as2 = (const float*)d_in[8];
    const float* ad2 = (const float*)d_in[9];
    const float* b2  = (const float*)d_in[10];
    const float* mw1 = (const float*)d_in[11];
    const float* mb1 = (const float*)d_in[12];
    const float* mw2 = (const float*)d_in[13];
    const float* mb2 = (const float*)d_in[14];
    const float* ow  = (const float*)d_in[15];
    const float* ob  = (const float*)d_in[16];
    float* out = (float*)d_out;

    cudaFuncSetAttribute(fgemm_kernel, cudaFuncAttributeMaxDynamicSharedMemorySize, FS_TOTAL);

    build_kernel<<<394, 256>>>(actions, nodef, W1, as1, ad1, ei, W2);
    conv1_kernel<<<282, 256>>>();
    fgemm_kernel<<<250, 256, FS_TOTAL>>>(W1, b1, as2, ad2);
    conv2_kernel<<<1000, 256>>>(b2);
    mlp1_kernel<<<NCHUNK, 128>>>(mw1);
    reduce_kernel<<<16, 128>>>(mb1);
    tail_kernel<<<8, 256>>>(mw2, mb2, ow, ob, out);
}